// round 4
// baseline (speedup 1.0000x reference)
#include <cuda_runtime.h>

#define NXC 512
#define NYC 512
#define PHW 3
#define PP 6                 // patch size = 2*PHW
#define BB 128
#define SS 1024
#define TILE 32              // output tile edge
#define TPD 16               // tiles per image dim = 512/32
#define NTILES (BB * TPD * TPD)   // 32768
#define CAP 96               // max sources per tile bin (mean ~5.3)

// 1/(sqrt(2)*sigma), sigma=0.92
__device__ __forceinline__ float inv_alpha() { return 1.0f / (1.41421356237309515f * 0.92f); }

__device__ int g_cnt[NTILES];
__device__ int g_bin[NTILES * CAP];

__global__ void zero_counts_kernel() {
    int i = blockIdx.x * blockDim.x + threadIdx.x;
    if (i < NTILES) g_cnt[i] = 0;
}

__global__ void bin_kernel(const float* __restrict__ z) {
    int gid = blockIdx.x * blockDim.x + threadIdx.x;
    if (gid >= BB * SS) return;
    int b = gid >> 10;
    int s = gid & (SS - 1);

    float x0 = __ldg(&z[b * 2 * SS + s]);
    float y0 = __ldg(&z[b * 2 * SS + SS + s]);

    int patchx = __float2int_rn(x0) - PHW;   // row of patch origin
    int patchy = __float2int_rn(y0) - PHW;   // col of patch origin
    // reference: valid iff 0 <= patch < N - P  (strict)
    if (patchx < 0 || patchx >= NXC - PP || patchy < 0 || patchy >= NYC - PP) return;

    int tr0 = patchx >> 5, tr1 = (patchx + PP - 1) >> 5;
    int tc0 = patchy >> 5, tc1 = (patchy + PP - 1) >> 5;
    for (int tr = tr0; tr <= tr1; ++tr) {
        for (int tc = tc0; tc <= tc1; ++tc) {
            int bin = ((b * TPD) + tr) * TPD + tc;
            int pos = atomicAdd(&g_cnt[bin], 1);
            if (pos < CAP) g_bin[bin * CAP + pos] = gid;
        }
    }
}

__global__ __launch_bounds__(256) void render_kernel(const float* __restrict__ z,
                                                     float* __restrict__ out) {
    __shared__ int   s_px[CAP];
    __shared__ int   s_py[CAP];
    __shared__ float s_lx[CAP * PP];
    __shared__ float s_ly[CAP * PP];

    int bin = blockIdx.x;
    int b  = bin >> 8;
    int tr = (bin >> 4) & (TPD - 1);
    int tc = bin & (TPD - 1);
    int tid = threadIdx.x;

    int n = g_cnt[bin];
    if (n > CAP) n = CAP;

    // setup: one thread per source computes patch profile into smem
    if (tid < n) {
        int gid = g_bin[bin * CAP + tid];
        int sb = gid >> 10;
        int ss = gid & (SS - 1);
        float x0 = __ldg(&z[sb * 2 * SS + ss]);
        float y0 = __ldg(&z[sb * 2 * SS + SS + ss]);
        int patchx = __float2int_rn(x0) - PHW;
        int patchy = __float2int_rn(y0) - PHW;
        float x0p = x0 - (float)patchx;
        float y0p = y0 - (float)patchy;
        const float ia = inv_alpha();

        float ex[PP + 1], ey[PP + 1];
#pragma unroll
        for (int k = 0; k <= PP; k++) {
            float kk = (float)k - 0.5f;
            ex[k] = erff((kk - x0p) * ia);
            ey[k] = erff((kk - y0p) * ia);
        }
        s_px[tid] = patchx;
        s_py[tid] = patchy;
#pragma unroll
        for (int k = 0; k < PP; k++) {
            s_lx[tid * PP + k] = 500.0f * (ex[k + 1] - ex[k]);   // i0 * 0.5 folded
            s_ly[tid * PP + k] = 0.5f * (ey[k + 1] - ey[k]);
        }
    }
    __syncthreads();

    // each thread owns 1 row x 4 consecutive cols -> one float4 store
    int row  = tid >> 3;                    // 0..31 within tile
    int cg   = (tid & 7) << 2;              // col group start 0..28
    int grow = tr * TILE + row;             // global row
    int gcol = tc * TILE + cg;              // global col (of 4)

    float4 acc = make_float4(0.f, 0.f, 0.f, 0.f);

    for (int s = 0; s < n; ++s) {
        int dr = grow - s_px[s];
        if ((unsigned)dr < (unsigned)PP) {
            float lxv = s_lx[s * PP + dr];
            int dc = gcol - s_py[s];
#pragma unroll
            for (int c = 0; c < 4; ++c) {
                int d = dc + c;
                if ((unsigned)d < (unsigned)PP) {
                    float v = lxv * s_ly[s * PP + d];
                    if (c == 0) acc.x += v;
                    else if (c == 1) acc.y += v;
                    else if (c == 2) acc.z += v;
                    else acc.w += v;
                }
            }
        }
    }

    float4* dst = (float4*)(out + (size_t)b * NXC * NYC + grow * NYC + gcol);
    *dst = acc;
}

extern "C" void kernel_launch(void* const* d_in, const int* in_sizes, int n_in,
                              void* d_out, int out_size) {
    const float* z = (const float*)d_in[0];
    float* out = (float*)d_out;

    zero_counts_kernel<<<(NTILES + 255) / 256, 256>>>();
    bin_kernel<<<(BB * SS + 255) / 256, 256>>>(z);
    render_kernel<<<NTILES, 256>>>(z, out);
}

// round 5
// speedup vs baseline: 1.3674x; 1.3674x over previous
#include <cuda_runtime.h>

#define NXC 512
#define NYC 512
#define PHW 3
#define PP 6                  // patch size
#define BB 128
#define SS 1024
#define BH 16                 // band height (rows)
#define BANDS_PER_IMG (NXC / BH)      // 32
#define NBANDS (BB * BANDS_PER_IMG)   // 4096
#define CAP 128               // max sources per band (mean ~42)

__device__ __forceinline__ float inv_alpha() { return 1.0f / (1.41421356237309515f * 0.92f); }

__device__ int    g_cnt[NBANDS];              // zero-init at load; each render block re-zeroes its own
__device__ float2 g_src[NBANDS * CAP];

__global__ void bin_kernel(const float* __restrict__ z) {
    int gid = blockIdx.x * blockDim.x + threadIdx.x;
    if (gid >= BB * SS) return;
    int b = gid >> 10;
    int s = gid & (SS - 1);

    float x0 = __ldg(&z[b * 2 * SS + s]);
    float y0 = __ldg(&z[b * 2 * SS + SS + s]);

    int patchx = __float2int_rn(x0) - PHW;
    int patchy = __float2int_rn(y0) - PHW;
    if (patchx < 0 || patchx >= NXC - PP || patchy < 0 || patchy >= NYC - PP) return;

    int band0 = patchx >> 4;                 // first band touched
    int band1 = (patchx + PP - 1) >> 4;      // last band touched (band0 or band0+1)
    for (int bd = band0; bd <= band1; ++bd) {
        int bin = b * BANDS_PER_IMG + bd;
        int pos = atomicAdd(&g_cnt[bin], 1);
        if (pos < CAP) g_src[bin * CAP + pos] = make_float2(x0, y0);
    }
}

__global__ __launch_bounds__(256) void render_kernel(float* __restrict__ out) {
    __shared__ float band[BH * NYC];          // 32 KB accumulation buffer
    __shared__ int   s_px[CAP];
    __shared__ int   s_py[CAP];
    __shared__ float s_lx[CAP * PP];
    __shared__ float s_ly[CAP * PP];
    __shared__ int   s_n;

    int bin = blockIdx.x;
    int b   = bin >> 5;                       // image
    int r0  = (bin & (BANDS_PER_IMG - 1)) << 4;  // first global row of band
    int tid = threadIdx.x;
    int wid = tid >> 5;
    int lane = tid & 31;

    if (tid == 0) {
        int n = g_cnt[bin];
        s_n = (n > CAP) ? CAP : n;
        g_cnt[bin] = 0;                       // restore for next graph replay
    }

    // zero the band buffer: 2048 float4 / 256 threads = 8 each
    float4* bs = (float4*)band;
#pragma unroll
    for (int k = 0; k < 8; ++k)
        bs[k * 256 + tid] = make_float4(0.f, 0.f, 0.f, 0.f);
    __syncthreads();

    int n = s_n;

    // per-source profile setup: one thread per source
    if (tid < n) {
        float2 xy = g_src[bin * CAP + tid];
        float x0 = xy.x, y0 = xy.y;
        int patchx = __float2int_rn(x0) - PHW;
        int patchy = __float2int_rn(y0) - PHW;
        float x0p = x0 - (float)patchx;
        float y0p = y0 - (float)patchy;
        const float ia = inv_alpha();

        float ex[PP + 1], ey[PP + 1];
#pragma unroll
        for (int k = 0; k <= PP; k++) {
            float kk = (float)k - 0.5f;
            ex[k] = erff((kk - x0p) * ia);
            ey[k] = erff((kk - y0p) * ia);
        }
        s_px[tid] = patchx;
        s_py[tid] = patchy;
#pragma unroll
        for (int k = 0; k < PP; k++) {
            s_lx[tid * PP + k] = 500.0f * (ex[k + 1] - ex[k]);  // i0*0.5 folded
            s_ly[tid * PP + k] = 0.5f * (ey[k + 1] - ey[k]);
        }
    }
    __syncthreads();

    // accumulate: warp w takes sources w, w+8, ...; lanes cover the 36 patch pixels
    for (int s = wid; s < n; s += 8) {
        int rl = s_px[s] - r0;                // local row of patch origin, in [-5, 15]
        int py = s_py[s];
#pragma unroll
        for (int rep = 0; rep < 2; ++rep) {
            int p = lane + rep * 32;
            if (p < PP * PP) {
                int i = p / PP;
                int j = p - i * PP;
                int r = rl + i;
                if ((unsigned)r < (unsigned)BH) {
                    float v = s_lx[s * PP + i] * s_ly[s * PP + j];
                    atomicAdd(&band[r * NYC + py + j], v);
                }
            }
        }
    }
    __syncthreads();

    // stream band to gmem: fully coalesced float4
    float4* dst = (float4*)(out + (size_t)b * NXC * NYC + (size_t)r0 * NYC);
#pragma unroll
    for (int k = 0; k < 8; ++k) {
        int f = k * 256 + tid;                // float4 index within band
        dst[f] = bs[f];
    }
}

extern "C" void kernel_launch(void* const* d_in, const int* in_sizes, int n_in,
                              void* d_out, int out_size) {
    const float* z = (const float*)d_in[0];
    float* out = (float*)d_out;

    bin_kernel<<<(BB * SS + 255) / 256, 256>>>(z);
    render_kernel<<<NBANDS, 256>>>(out);
}

// round 6
// speedup vs baseline: 1.4261x; 1.0429x over previous
#include <cuda_runtime.h>

#define NXC 512
#define NYC 512
#define PHW 3
#define PP 6                  // patch size
#define BB 128
#define SS 1024
#define BH 16                 // band height (rows)
#define BW 516                // padded band width (bank-conflict fix: 516 mod 32 = 4)
#define BANDS_PER_IMG (NXC / BH)      // 32
#define NBANDS (BB * BANDS_PER_IMG)   // 4096
#define CAP 128               // max sources per band (mean ~42, +13 sigma headroom)

__device__ __forceinline__ float inv_alpha() { return 1.0f / (1.41421356237309515f * 0.92f); }

__device__ int    g_cnt[NBANDS];              // zero at load; each render block re-zeroes its own
__device__ float2 g_src[NBANDS * CAP];

__global__ void bin_kernel(const float* __restrict__ z) {
    int gid = blockIdx.x * blockDim.x + threadIdx.x;
    if (gid >= BB * SS) return;
    int b = gid >> 10;
    int s = gid & (SS - 1);

    float x0 = __ldg(&z[b * 2 * SS + s]);
    float y0 = __ldg(&z[b * 2 * SS + SS + s]);

    int patchx = __float2int_rn(x0) - PHW;
    int patchy = __float2int_rn(y0) - PHW;
    if (patchx < 0 || patchx >= NXC - PP || patchy < 0 || patchy >= NYC - PP) return;

    int band0 = patchx >> 4;
    int band1 = (patchx + PP - 1) >> 4;
    for (int bd = band0; bd <= band1; ++bd) {
        int bin = b * BANDS_PER_IMG + bd;
        int pos = atomicAdd(&g_cnt[bin], 1);
        if (pos < CAP) g_src[bin * CAP + pos] = make_float2(x0, y0);
    }
}

__global__ __launch_bounds__(256) void render_kernel(float* __restrict__ out) {
    __shared__ float band[BH * BW];           // 33 KB padded accumulation buffer
    __shared__ int   s_px[CAP];
    __shared__ int   s_py[CAP];
    __shared__ float s_lx[CAP * PP];
    __shared__ float s_ly[CAP * PP];
    __shared__ int   s_n;

    int bin = blockIdx.x;
    int b   = bin >> 5;
    int r0  = (bin & (BANDS_PER_IMG - 1)) << 4;
    int tid = threadIdx.x;
    int wid = tid >> 5;
    int lane = tid & 31;

    if (tid == 0) {
        int n = g_cnt[bin];
        s_n = (n > CAP) ? CAP : n;
        g_cnt[bin] = 0;                       // restore for next graph replay
    }
    __syncthreads();
    int n = s_n;

    // zero padded band: 2064 float4 over 256 threads
    float4* bz = (float4*)band;
    for (int i = tid; i < BH * BW / 4; i += 256)
        bz[i] = make_float4(0.f, 0.f, 0.f, 0.f);

    // per-source profile setup (threads tid<n; runs alongside zeroing warps)
    if (tid < n) {
        float2 xy = g_src[bin * CAP + tid];
        float x0 = xy.x, y0 = xy.y;
        int patchx = __float2int_rn(x0) - PHW;
        int patchy = __float2int_rn(y0) - PHW;
        float x0p = x0 - (float)patchx;
        float y0p = y0 - (float)patchy;
        const float ia = inv_alpha();

        float ex[PP + 1], ey[PP + 1];
#pragma unroll
        for (int k = 0; k <= PP; k++) {
            float kk = (float)k - 0.5f;
            ex[k] = erff((kk - x0p) * ia);
            ey[k] = erff((kk - y0p) * ia);
        }
        s_px[tid] = patchx;
        s_py[tid] = patchy;
#pragma unroll
        for (int k = 0; k < PP; k++) {
            s_lx[tid * PP + k] = 500.0f * (ex[k + 1] - ex[k]);  // i0*0.5 folded
            s_ly[tid * PP + k] = 0.5f * (ey[k + 1] - ey[k]);
        }
    }
    __syncthreads();

    // accumulate: warp w takes sources w, w+8, ...; lanes cover the 36 patch pixels
    for (int s = wid; s < n; s += 8) {
        int rl = s_px[s] - r0;                // local patch-origin row, in [-5, 15]
        int py = s_py[s];
#pragma unroll
        for (int rep = 0; rep < 2; ++rep) {
            int p = lane + rep * 32;
            if (p < PP * PP) {
                int i = p / PP;
                int j = p - i * PP;
                int r = rl + i;
                if ((unsigned)r < (unsigned)BH) {
                    float v = s_lx[s * PP + i] * s_ly[s * PP + j];
                    atomicAdd(&band[r * BW + py + j], v);   // bank = (4r + py + j) % 32 -> deg <= 2
                }
            }
        }
    }
    __syncthreads();

    // stream band to gmem: coalesced float4 (skip the 4-float row padding)
    float4* dst = (float4*)(out + (size_t)b * NXC * NYC + (size_t)r0 * NYC);
#pragma unroll
    for (int k = 0; k < 8; ++k) {
        int f = k * 256 + tid;                // output float4 index within 16x512 band
        int row = f >> 7;
        int c4  = f & 127;
        float4 v = *(float4*)&band[row * BW + (c4 << 2)];
        dst[f] = v;
    }
}

extern "C" void kernel_launch(void* const* d_in, const int* in_sizes, int n_in,
                              void* d_out, int out_size) {
    const float* z = (const float*)d_in[0];
    float* out = (float*)d_out;

    bin_kernel<<<(BB * SS + 255) / 256, 256>>>(z);
    render_kernel<<<NBANDS, 256>>>(out);
}